// round 5
// baseline (speedup 1.0000x reference)
#include <cuda_runtime.h>
#include <cuda_fp16.h>
#include <cuda_bf16.h>

// Problem constants
#define B_   32
#define N_   4096
#define DK_  128
#define H_   128
#define A_   128
#define CH_  16
#define TILE_ 256
#define GRID_ 512

// ---------------- scratch (device globals) ---------------------------------
__device__ __half g_zfh[B_*N_*A_];     // fp16 z@W_z + b_attn (33.5MB)
__device__ __half g_zh[B_*N_*DK_];     // fp16 copy of z (33.5MB)
__device__ float g_s[B_*DK_];          // prev context (LSTM input)
__device__ float g_hbuf[2][B_*H_];     // double-buffered hidden state
__device__ float g_c[B_*H_];           // cell state
__device__ float g_xn[B_*2*H_];        // [h_new | c_new] per batch
__device__ float g_dec[B_*A_];         // dec_fea
__device__ float g_WxT[A_*2*H_];       // transposed W_x: [a][k]
__device__ float g_Sp[B_*CH_];         // partial softmax denominators
__device__ float g_CTp[B_*CH_*DK_];    // partial context vectors
__device__ float g_clp[GRID_];         // per-block closs partials (deterministic)
__device__ unsigned g_bcnt;            // grid barrier counter
__device__ unsigned g_bgen;            // grid barrier generation

__device__ __forceinline__ float tanh_fast(float x) {
    float y; asm("tanh.approx.f32 %0, %1;" : "=f"(y) : "f"(x)); return y;
}
__device__ __forceinline__ float sigmoid_f(float x) {
    return 1.0f / (1.0f + __expf(-x));
}

// Software grid barrier. Safe: all GRID_ blocks co-resident
// (launch_bounds(256,4) -> 4 blocks/SM, 148*4=592 >= 512).
__device__ __forceinline__ void grid_sync() {
    __syncthreads();
    if (threadIdx.x == 0) {
        __threadfence();
        unsigned gen = *(volatile unsigned*)&g_bgen;
        if (atomicAdd(&g_bcnt, 1u) == GRID_ - 1u) {
            g_bcnt = 0;
            __threadfence();
            *(volatile unsigned*)&g_bgen = gen + 1u;
        } else {
            while (*(volatile unsigned*)&g_bgen == gen) __nanosleep(64);
        }
        __threadfence();
    }
    __syncthreads();
}

// ---------------- z_fea = z @ W_z + b_attn (fp16 out) + z fp16 copy --------
__global__ void zfea_kernel(const float* __restrict__ z, const float* __restrict__ Wz,
                            const float* __restrict__ battn) {
    __shared__ float zs[64*DK_];
    int t = threadIdx.x;
    int rowBase = blockIdx.x * 64;
    const float* zsrc = z + (size_t)rowBase * DK_;
    #pragma unroll
    for (int k = 0; k < 32; k++) zs[t + k*256] = zsrc[t + k*256];
    __syncthreads();

    // fp16 copy of z (16 half2 per thread)
    {
        __half2* zhp = (__half2*)(g_zh + (size_t)rowBase * DK_);
        #pragma unroll
        for (int k = 0; k < 16; k++) {
            int h2 = t + k*256;
            zhp[h2] = __floats2half2_rn(zs[h2*2], zs[h2*2 + 1]);
        }
    }

    int tx = t & 31, ty = t >> 5;
    float acc[8][4];
    #pragma unroll
    for (int i = 0; i < 8; i++)
        #pragma unroll
        for (int c = 0; c < 4; c++) acc[i][c] = 0.0f;

    const float4* Wz4 = (const float4*)Wz;
    #pragma unroll 4
    for (int d = 0; d < DK_; d++) {
        float4 w = __ldg(&Wz4[d*32 + tx]);
        #pragma unroll
        for (int i = 0; i < 8; i++) {
            float zv = zs[(ty + 8*i)*DK_ + d];
            acc[i][0] = fmaf(zv, w.x, acc[i][0]);
            acc[i][1] = fmaf(zv, w.y, acc[i][1]);
            acc[i][2] = fmaf(zv, w.z, acc[i][2]);
            acc[i][3] = fmaf(zv, w.w, acc[i][3]);
        }
    }
    float4 bb = __ldg(&((const float4*)battn)[tx]);
    __half2* outp = (__half2*)g_zfh;
    #pragma unroll
    for (int i = 0; i < 8; i++) {
        size_t r = rowBase + ty + 8*i;
        outp[r*64 + tx*2]     = __floats2half2_rn(acc[i][0] + bb.x, acc[i][1] + bb.y);
        outp[r*64 + tx*2 + 1] = __floats2half2_rn(acc[i][2] + bb.z, acc[i][3] + bb.w);
    }
}

// ---------------- persistent step loop: gates -> dec -> score -> finalize --
__global__ __launch_bounds__(256, 4) void persistent_kernel(
        float* __restrict__ out, int T, int out_size,
        const float* __restrict__ Wih, const float* __restrict__ Whh,
        const float* __restrict__ bih, const float* __restrict__ bhh,
        const float* __restrict__ Wx,
        const float* __restrict__ mask,
        const float* __restrict__ wc, const float* __restrict__ v,
        const float* __restrict__ h0, const float* __restrict__ c0) {
    int bid = blockIdx.x;
    int tid = threadIdx.x;
    int warp = tid >> 5, lane = tid & 31;
    __shared__ float shm[136];

    int sb = bid >> 4;                    // score/finalize: batch
    int schunk = bid & 15;                // score/finalize: chunk

    // ---- one-time init ----
    if (bid < 128) {                      // W_x transpose: 32768 elems
        int i = bid*256 + tid;
        int k = i >> 7, a = i & 127;
        g_WxT[a*(2*H_) + k] = Wx[k*A_ + a];
    }
    if (bid >= 128 && bid < 144) {        // state init: 4096 elems
        int idx = (bid-128)*256 + tid;
        g_s[idx] = 0.0f;
        g_hbuf[0][idx] = h0[idx];
        g_c[idx] = c0[idx];
    }
    // row-owned registers: thread owns row n = schunk*256 + tid of batch sb
    float cov_reg = 0.0f;                 // coverage lives here for all T steps
    float p_reg = 0.0f;                   // unnormalized exp score (C -> D)
    float m_reg = __ldg(&mask[sb*N_ + schunk*256 + tid]);
    float closs_acc = 0.0f;
    grid_sync();

    size_t OUT_ATT = (size_t)B_ * T * DK_;

    for (int t = 0; t < T; t++) {
        int hb = t & 1;

        // ======== Phase A: LSTM gates + c/h update (blocks 0..127) ========
        if (bid < 128) {
            int j = bid;                  // hidden unit
            int half = lane >> 4;         // 0: s/Wih  1: h/Whh
            int koff2 = (lane & 15) * 2;  // float4 index within row
            const float4* Wih4 = (const float4*)Wih;
            const float4* Whh4 = (const float4*)Whh;
            #pragma unroll 4
            for (int i = 0; i < 16; i++) {
                int o = warp*16 + i;      // output id: gate*32 + b
                int gate = o >> 5, bb = o & 31;
                int r = gate*H_ + j;      // weight row
                const float4* Wp4 = half ? Whh4 : Wih4;
                const float4* xp4 = half ? (const float4*)&g_hbuf[hb][bb*H_]
                                         : (const float4*)&g_s[bb*DK_];
                float4 w0 = __ldg(&Wp4[r*32 + koff2]);
                float4 w1 = __ldg(&Wp4[r*32 + koff2 + 1]);
                float4 x0 = xp4[koff2];
                float4 x1 = xp4[koff2 + 1];
                float acc = w0.x*x0.x + w0.y*x0.y + w0.z*x0.z + w0.w*x0.w
                          + w1.x*x1.x + w1.y*x1.y + w1.z*x1.z + w1.w*x1.w;
                #pragma unroll
                for (int off = 16; off > 0; off >>= 1)
                    acc += __shfl_xor_sync(0xffffffffu, acc, off);
                if (lane == 0) shm[o] = acc + __ldg(&bih[r]) + __ldg(&bhh[r]);
            }
            __syncthreads();
            if (tid < 32) {
                int bb = tid;
                float ig = sigmoid_f(shm[bb]);
                float fg = sigmoid_f(shm[32 + bb]);
                float gg = tanhf(shm[64 + bb]);
                float og = sigmoid_f(shm[96 + bb]);
                float cold = g_c[bb*H_ + j];
                float cn = fg * cold + ig * gg;
                float hn = og * tanhf(cn);
                g_c[bb*H_ + j] = cn;
                g_hbuf[hb ^ 1][bb*H_ + j] = hn;
                g_xn[bb*2*H_ + j] = hn;
                g_xn[bb*2*H_ + H_ + j] = cn;
            }
        }
        grid_sync();

        // ======== Phase B: dec_fea = xn @ W_x (blocks 0..127) ========
        if (bid < 128) {
            int a = bid;
            const float4* WxT4 = (const float4*)g_WxT;
            float4 w0 = WxT4[a*64 + lane*2];
            float4 w1 = WxT4[a*64 + lane*2 + 1];
            #pragma unroll
            for (int i = 0; i < 4; i++) {
                int bb = warp*4 + i;
                const float4* xn4 = (const float4*)&g_xn[bb*2*H_];
                float4 x0 = xn4[lane*2];
                float4 x1 = xn4[lane*2 + 1];
                float acc = w0.x*x0.x + w0.y*x0.y + w0.z*x0.z + w0.w*x0.w
                          + w1.x*x1.x + w1.y*x1.y + w1.z*x1.z + w1.w*x1.w;
                #pragma unroll
                for (int off = 16; off > 0; off >>= 1)
                    acc += __shfl_xor_sync(0xffffffffu, acc, off);
                if (lane == 0) g_dec[bb*A_ + a] = acc;
            }
        }
        grid_sync();

        // ======== Phase C: attention scores + partial context (all) ========
        {
            int b = sb, chunk = schunk;
            float4 dec4 = *(const float4*)&g_dec[b*A_ + lane*4];
            float4 wc4  = __ldg(&((const float4*)wc)[lane]);
            float4 v4   = __ldg(&((const float4*)v)[lane]);

            float4 ct = make_float4(0.f, 0.f, 0.f, 0.f);
            float Sacc = 0.0f;
            int n0 = chunk * TILE_ + warp * 32;
            const __half2* zfh = (const __half2*)g_zfh;
            const __half2* zh  = (const __half2*)g_zh;

            #pragma unroll 4
            for (int r = 0; r < 32; r++) {
                int idx = b*N_ + n0 + r;
                float cov = __shfl_sync(0xffffffffu, cov_reg, r);
                float m   = __shfl_sync(0xffffffffu, m_reg, r);
                float2 fa = __half22float2(zfh[(size_t)idx*64 + lane*2]);
                float2 fb = __half22float2(zfh[(size_t)idx*64 + lane*2 + 1]);
                float t0 = tanh_fast(fmaf(cov, wc4.x, fa.x) + dec4.x);
                float t1 = tanh_fast(fmaf(cov, wc4.y, fa.y) + dec4.y);
                float t2 = tanh_fast(fmaf(cov, wc4.z, fb.x) + dec4.z);
                float t3 = tanh_fast(fmaf(cov, wc4.w, fb.y) + dec4.w);
                float e = v4.x*t0 + v4.y*t1 + v4.z*t2 + v4.w*t3;
                #pragma unroll
                for (int off = 16; off > 0; off >>= 1)
                    e += __shfl_xor_sync(0xffffffffu, e, off);
                // e bounded by ||v||_1 (~9): exp cannot overflow, skip global max
                float p = (m > 0.0f) ? __expf(e) : 0.0f;
                float2 za = __half22float2(zh[(size_t)idx*64 + lane*2]);
                float2 zb = __half22float2(zh[(size_t)idx*64 + lane*2 + 1]);
                ct.x = fmaf(p, za.x, ct.x);
                ct.y = fmaf(p, za.y, ct.y);
                ct.z = fmaf(p, zb.x, ct.z);
                ct.w = fmaf(p, zb.y, ct.w);
                if (lane == r) p_reg = p;    // row owner keeps its score
                Sacc += p;                   // identical across lanes
            }

            if (tid < DK_) shm[tid] = 0.0f;
            if (lane == 0) shm[128 + warp] = Sacc;
            __syncthreads();
            atomicAdd(&shm[lane*4 + 0], ct.x);
            atomicAdd(&shm[lane*4 + 1], ct.y);
            atomicAdd(&shm[lane*4 + 2], ct.z);
            atomicAdd(&shm[lane*4 + 3], ct.w);
            __syncthreads();
            if (tid < DK_)
                g_CTp[(b*CH_ + chunk)*DK_ + tid] = shm[tid];
            if (tid == 0) {
                float S = 0.0f;
                #pragma unroll
                for (int w = 0; w < 8; w++) S += shm[128 + w];
                g_Sp[b*CH_ + chunk] = S;
            }
            __syncthreads();
        }
        grid_sync();

        // ======== Phase D: finalize (all blocks) ========
        {
            int b = sb, seg = schunk;
            if (tid < CH_) shm[tid] = g_Sp[b*CH_ + tid];
            __syncthreads();
            float S = 0.0f;
            #pragma unroll
            for (int ch = 0; ch < CH_; ch++) S += shm[ch];
            float invS = 1.0f / S;

            if (seg == 0 && tid < DK_) {
                float ctv = 0.0f;
                #pragma unroll
                for (int ch = 0; ch < CH_; ch++)
                    ctv += g_CTp[(b*CH_ + ch)*DK_ + tid];
                ctv *= invS;
                out[(size_t)(b*T + t)*DK_ + tid] = ctv;
                g_s[b*DK_ + tid] = ctv;         // next LSTM input
            }

            int n = seg*256 + tid;
            float attn = p_reg * invS;
            float cl = fminf(attn, cov_reg);    // coverage BEFORE update
            cov_reg += attn;
            out[OUT_ATT + (size_t)(b*T + t)*N_ + n] = attn;

            #pragma unroll
            for (int off = 16; off > 0; off >>= 1)
                cl += __shfl_xor_sync(0xffffffffu, cl, off);
            __syncthreads();                    // shm reuse guard
            if (lane == 0) shm[16 + warp] = cl;
            __syncthreads();
            if (tid == 0) {
                float s = 0.0f;
                #pragma unroll
                for (int w = 0; w < 8; w++) s += shm[16 + w];
                closs_acc += s;
            }
        }
        grid_sync();
    }

    // deterministic closs: ordered reduction of per-block partials
    if (tid == 0) g_clp[bid] = closs_acc;
    grid_sync();
    if (bid == 0 && tid == 0) {
        float s = 0.0f;
        for (int i = 0; i < GRID_; i++) s += g_clp[i];
        out[out_size - 1] = s / (float)B_;
    }
}

// ---------------- host driver ----------------------------------------------
extern "C" void kernel_launch(void* const* d_in, const int* in_sizes, int n_in,
                              void* d_out, int out_size) {
    const float* z     = (const float*)d_in[0];
    const float* mask  = (const float*)d_in[1];
    const float* h0    = (const float*)d_in[2];
    const float* c0    = (const float*)d_in[3];
    const float* W_ih  = (const float*)d_in[4];
    const float* W_hh  = (const float*)d_in[5];
    const float* b_ih  = (const float*)d_in[6];
    const float* b_hh  = (const float*)d_in[7];
    const float* W_x   = (const float*)d_in[8];
    const float* W_z   = (const float*)d_in[9];
    const float* w_c   = (const float*)d_in[10];
    const float* b_attn= (const float*)d_in[11];
    const float* v     = (const float*)d_in[12];
    float* out = (float*)d_out;

    int T = (out_size - 1) / (B_ * (DK_ + N_));

    zfea_kernel<<<(B_*N_)/64, 256>>>(z, W_z, b_attn);
    persistent_kernel<<<GRID_, 256>>>(out, T, out_size,
                                      W_ih, W_hh, b_ih, b_hh, W_x,
                                      mask, w_c, v, h0, c0);
}

// round 7
// speedup vs baseline: 1.5586x; 1.5586x over previous
#include <cuda_runtime.h>
#include <cuda_fp16.h>
#include <cuda_bf16.h>

// Problem constants
#define B_   32
#define N_   4096
#define DK_  128
#define H_   128
#define A_   128
#define CH_  16
#define TILE_ 256
#define GRID_ 512

// ---------------- scratch (device globals) ---------------------------------
// Interleaved fp16: per row idx, lane l owns halves [l*8..l*8+7] =
// {zfea[4l..4l+3], z[4l..4l+3]} -> one uint4 (16B) load per (row, lane).
__device__ __half g_zi[(size_t)B_*N_*256];   // 67MB
__device__ float g_s[B_*DK_];          // prev context (LSTM input)
__device__ float g_hbuf[2][B_*H_];     // double-buffered hidden state
__device__ float g_c[B_*H_];           // cell state
__device__ float g_xn[B_*2*H_];        // [h_new | c_new] per batch
__device__ float g_dec[B_*A_];         // dec_fea
__device__ float g_WxT[A_*2*H_];       // transposed W_x: [a][k]
__device__ float g_Sp[B_*CH_];         // partial softmax denominators
__device__ float g_CTp[B_*CH_*DK_];    // partial context vectors
__device__ float g_clp[GRID_];         // per-block closs partials (deterministic)
__device__ unsigned g_bcnt;            // grid barrier counter
__device__ unsigned g_bgen;            // grid barrier generation

__device__ __forceinline__ float tanh_fast(float x) {
    float y; asm("tanh.approx.f32 %0, %1;" : "=f"(y) : "f"(x)); return y;
}
__device__ __forceinline__ float sigmoid_f(float x) {
    return 1.0f / (1.0f + __expf(-x));
}
__device__ __forceinline__ unsigned h2_to_u(__half2 h) {
    return *reinterpret_cast<unsigned*>(&h);
}
__device__ __forceinline__ float2 u_to_f2(unsigned u) {
    __half2 h = *reinterpret_cast<__half2*>(&u);
    return __half22float2(h);
}

// Software grid barrier. Safe: all GRID_ blocks co-resident
// (launch_bounds(256,4) -> 4 blocks/SM, 148*4=592 >= 512).
__device__ __forceinline__ void grid_sync() {
    __syncthreads();
    if (threadIdx.x == 0) {
        __threadfence();
        unsigned gen = *(volatile unsigned*)&g_bgen;
        if (atomicAdd(&g_bcnt, 1u) == GRID_ - 1u) {
            g_bcnt = 0;
            __threadfence();
            *(volatile unsigned*)&g_bgen = gen + 1u;
        } else {
            while (*(volatile unsigned*)&g_bgen == gen) __nanosleep(64);
        }
        __threadfence();
    }
    __syncthreads();
}

// ---------------- z_fea GEMM -> interleaved fp16 {zf|z} --------------------
__global__ void zfea_kernel(const float* __restrict__ z, const float* __restrict__ Wz,
                            const float* __restrict__ battn) {
    __shared__ float zs[64*DK_];
    int t = threadIdx.x;
    int rowBase = blockIdx.x * 64;
    const float* zsrc = z + (size_t)rowBase * DK_;
    #pragma unroll
    for (int k = 0; k < 32; k++) zs[t + k*256] = zsrc[t + k*256];
    __syncthreads();

    int tx = t & 31, ty = t >> 5;
    float acc[8][4];
    #pragma unroll
    for (int i = 0; i < 8; i++)
        #pragma unroll
        for (int c = 0; c < 4; c++) acc[i][c] = 0.0f;

    const float4* Wz4 = (const float4*)Wz;
    #pragma unroll 4
    for (int d = 0; d < DK_; d++) {
        float4 w = __ldg(&Wz4[d*32 + tx]);
        #pragma unroll
        for (int i = 0; i < 8; i++) {
            float zv = zs[(ty + 8*i)*DK_ + d];
            acc[i][0] = fmaf(zv, w.x, acc[i][0]);
            acc[i][1] = fmaf(zv, w.y, acc[i][1]);
            acc[i][2] = fmaf(zv, w.z, acc[i][2]);
            acc[i][3] = fmaf(zv, w.w, acc[i][3]);
        }
    }
    float4 bb = __ldg(&((const float4*)battn)[tx]);
    uint4* outp = (uint4*)g_zi;
    #pragma unroll
    for (int i = 0; i < 8; i++) {
        size_t r = rowBase + ty + 8*i;
        int lr = ty + 8*i;                 // local row in zs
        __half2 f0 = __floats2half2_rn(acc[i][0] + bb.x, acc[i][1] + bb.y);
        __half2 f1 = __floats2half2_rn(acc[i][2] + bb.z, acc[i][3] + bb.w);
        __half2 z0 = __floats2half2_rn(zs[lr*DK_ + tx*4],     zs[lr*DK_ + tx*4 + 1]);
        __half2 z1 = __floats2half2_rn(zs[lr*DK_ + tx*4 + 2], zs[lr*DK_ + tx*4 + 3]);
        uint4 pk;
        pk.x = h2_to_u(f0); pk.y = h2_to_u(f1);
        pk.z = h2_to_u(z0); pk.w = h2_to_u(z1);
        outp[r*32 + tx] = pk;
    }
}

// ---------------- persistent step loop: gates -> dec -> score -> finalize --
__global__ __launch_bounds__(256, 4) void persistent_kernel(
        float* __restrict__ out, int T, int out_size,
        const float* __restrict__ Wih, const float* __restrict__ Whh,
        const float* __restrict__ bih, const float* __restrict__ bhh,
        const float* __restrict__ Wx,
        const float* __restrict__ mask,
        const float* __restrict__ wc, const float* __restrict__ v,
        const float* __restrict__ h0, const float* __restrict__ c0) {
    int bid = blockIdx.x;
    int tid = threadIdx.x;
    int warp = tid >> 5, lane = tid & 31;
    __shared__ float shm[136];

    int sb = bid >> 4;                    // score/finalize: batch
    int schunk = bid & 15;                // score/finalize: chunk

    // ---- one-time init ----
    if (bid < 128) {                      // W_x transpose: 32768 elems
        int i = bid*256 + tid;
        int k = i >> 7, a = i & 127;
        g_WxT[a*(2*H_) + k] = Wx[k*A_ + a];
    }
    if (bid >= 128 && bid < 144) {        // state init: 4096 elems
        int idx = (bid-128)*256 + tid;
        g_s[idx] = 0.0f;
        g_hbuf[0][idx] = h0[idx];
        g_c[idx] = c0[idx];
    }
    // row-owned registers: thread owns row n = schunk*256 + tid of batch sb
    float cov_reg = 0.0f;                 // coverage lives here for all T steps
    float p_reg = 0.0f;                   // unnormalized exp score (C -> D)
    float m_reg = __ldg(&mask[sb*N_ + schunk*256 + tid]);
    float closs_acc = 0.0f;
    grid_sync();

    size_t OUT_ATT = (size_t)B_ * T * DK_;

    for (int t = 0; t < T; t++) {
        int hb = t & 1;

        // ======== Phase A: LSTM gates + c/h update (blocks 0..127) ========
        if (bid < 128) {
            int j = bid;                  // hidden unit
            int half = lane >> 4;         // 0: s/Wih  1: h/Whh
            int koff2 = (lane & 15) * 2;  // float4 index within row
            const float4* Wih4 = (const float4*)Wih;
            const float4* Whh4 = (const float4*)Whh;
            #pragma unroll 4
            for (int i = 0; i < 16; i++) {
                int o = warp*16 + i;      // output id: gate*32 + b
                int gate = o >> 5, bb = o & 31;
                int r = gate*H_ + j;      // weight row
                const float4* Wp4 = half ? Whh4 : Wih4;
                const float4* xp4 = half ? (const float4*)&g_hbuf[hb][bb*H_]
                                         : (const float4*)&g_s[bb*DK_];
                float4 w0 = __ldg(&Wp4[r*32 + koff2]);
                float4 w1 = __ldg(&Wp4[r*32 + koff2 + 1]);
                float4 x0 = xp4[koff2];
                float4 x1 = xp4[koff2 + 1];
                float acc = w0.x*x0.x + w0.y*x0.y + w0.z*x0.z + w0.w*x0.w
                          + w1.x*x1.x + w1.y*x1.y + w1.z*x1.z + w1.w*x1.w;
                #pragma unroll
                for (int off = 16; off > 0; off >>= 1)
                    acc += __shfl_xor_sync(0xffffffffu, acc, off);
                if (lane == 0) shm[o] = acc + __ldg(&bih[r]) + __ldg(&bhh[r]);
            }
            __syncthreads();
            if (tid < 32) {
                int bb = tid;
                float ig = sigmoid_f(shm[bb]);
                float fg = sigmoid_f(shm[32 + bb]);
                float gg = tanhf(shm[64 + bb]);
                float og = sigmoid_f(shm[96 + bb]);
                float cold = g_c[bb*H_ + j];
                float cn = fg * cold + ig * gg;
                float hn = og * tanhf(cn);
                g_c[bb*H_ + j] = cn;
                g_hbuf[hb ^ 1][bb*H_ + j] = hn;
                g_xn[bb*2*H_ + j] = hn;
                g_xn[bb*2*H_ + H_ + j] = cn;
            }
        }
        grid_sync();

        // ======== Phase B: dec_fea = xn @ W_x (blocks 0..127) ========
        if (bid < 128) {
            int a = bid;
            const float4* WxT4 = (const float4*)g_WxT;
            float4 w0 = WxT4[a*64 + lane*2];
            float4 w1 = WxT4[a*64 + lane*2 + 1];
            #pragma unroll
            for (int i = 0; i < 4; i++) {
                int bb = warp*4 + i;
                const float4* xn4 = (const float4*)&g_xn[bb*2*H_];
                float4 x0 = xn4[lane*2];
                float4 x1 = xn4[lane*2 + 1];
                float acc = w0.x*x0.x + w0.y*x0.y + w0.z*x0.z + w0.w*x0.w
                          + w1.x*x1.x + w1.y*x1.y + w1.z*x1.z + w1.w*x1.w;
                #pragma unroll
                for (int off = 16; off > 0; off >>= 1)
                    acc += __shfl_xor_sync(0xffffffffu, acc, off);
                if (lane == 0) g_dec[bb*A_ + a] = acc;
            }
        }
        grid_sync();

        // ======== Phase C: attention scores + partial context (all) ========
        {
            int b = sb, chunk = schunk;
            float4 dec4 = *(const float4*)&g_dec[b*A_ + lane*4];
            float4 wc4  = __ldg(&((const float4*)wc)[lane]);
            float4 v4   = __ldg(&((const float4*)v)[lane]);

            float4 ct = make_float4(0.f, 0.f, 0.f, 0.f);
            float Sacc = 0.0f;
            int n0 = chunk * TILE_ + warp * 32;
            const uint4* zi4 = (const uint4*)g_zi;

            #pragma unroll 4
            for (int r = 0; r < 32; r++) {
                size_t idx = (size_t)b*N_ + n0 + r;
                float cov = __shfl_sync(0xffffffffu, cov_reg, r);
                float m   = __shfl_sync(0xffffffffu, m_reg, r);
                uint4 raw = zi4[idx*32 + lane];       // one LDG.128: {zf x4, z x4}
                float2 fa = u_to_f2(raw.x);
                float2 fb = u_to_f2(raw.y);
                float t0 = tanh_fast(fmaf(cov, wc4.x, fa.x) + dec4.x);
                float t1 = tanh_fast(fmaf(cov, wc4.y, fa.y) + dec4.y);
                float t2 = tanh_fast(fmaf(cov, wc4.z, fb.x) + dec4.z);
                float t3 = tanh_fast(fmaf(cov, wc4.w, fb.y) + dec4.w);
                float e = v4.x*t0 + v4.y*t1 + v4.z*t2 + v4.w*t3;
                #pragma unroll
                for (int off = 16; off > 0; off >>= 1)
                    e += __shfl_xor_sync(0xffffffffu, e, off);
                // e bounded by ||v||_1 (~9): exp cannot overflow, skip global max
                float p = (m > 0.0f) ? __expf(e) : 0.0f;
                float2 za = u_to_f2(raw.z);
                float2 zb = u_to_f2(raw.w);
                ct.x = fmaf(p, za.x, ct.x);
                ct.y = fmaf(p, za.y, ct.y);
                ct.z = fmaf(p, zb.x, ct.z);
                ct.w = fmaf(p, zb.y, ct.w);
                if (lane == r) p_reg = p;    // row owner keeps its score
                Sacc += p;                   // identical across lanes
            }

            if (tid < DK_) shm[tid] = 0.0f;
            if (lane == 0) shm[128 + warp] = Sacc;
            __syncthreads();
            atomicAdd(&shm[lane*4 + 0], ct.x);
            atomicAdd(&shm[lane*4 + 1], ct.y);
            atomicAdd(&shm[lane*4 + 2], ct.z);
            atomicAdd(&shm[lane*4 + 3], ct.w);
            __syncthreads();
            if (tid < DK_)
                g_CTp[(b*CH_ + chunk)*DK_ + tid] = shm[tid];
            if (tid == 0) {
                float S = 0.0f;
                #pragma unroll
                for (int w = 0; w < 8; w++) S += shm[128 + w];
                g_Sp[b*CH_ + chunk] = S;
            }
            __syncthreads();
        }
        grid_sync();

        // ======== Phase D: finalize (all blocks) ========
        {
            int b = sb, seg = schunk;
            if (tid < CH_) shm[tid] = g_Sp[b*CH_ + tid];
            __syncthreads();
            float S = 0.0f;
            #pragma unroll
            for (int ch = 0; ch < CH_; ch++) S += shm[ch];
            float invS = 1.0f / S;

            if (seg == 0 && tid < DK_) {
                float ctv = 0.0f;
                #pragma unroll
                for (int ch = 0; ch < CH_; ch++)
                    ctv += g_CTp[(b*CH_ + ch)*DK_ + tid];
                ctv *= invS;
                out[(size_t)(b*T + t)*DK_ + tid] = ctv;
                g_s[b*DK_ + tid] = ctv;         // next LSTM input
            }

            int n = seg*256 + tid;
            float attn = p_reg * invS;
            float cl = fminf(attn, cov_reg);    // coverage BEFORE update
            cov_reg += attn;
            out[OUT_ATT + (size_t)(b*T + t)*N_ + n] = attn;

            #pragma unroll
            for (int off = 16; off > 0; off >>= 1)
                cl += __shfl_xor_sync(0xffffffffu, cl, off);
            __syncthreads();                    // shm reuse guard
            if (lane == 0) shm[16 + warp] = cl;
            __syncthreads();
            if (tid == 0) {
                float s = 0.0f;
                #pragma unroll
                for (int w = 0; w < 8; w++) s += shm[16 + w];
                closs_acc += s;
            }
        }
        grid_sync();
    }

    // deterministic closs: ordered reduction of per-block partials
    if (tid == 0) g_clp[bid] = closs_acc;
    grid_sync();
    if (bid == 0 && tid == 0) {
        float s = 0.0f;
        for (int i = 0; i < GRID_; i++) s += g_clp[i];
        out[out_size - 1] = s / (float)B_;
    }
}

// ---------------- host driver ----------------------------------------------
extern "C" void kernel_launch(void* const* d_in, const int* in_sizes, int n_in,
                              void* d_out, int out_size) {
    const float* z     = (const float*)d_in[0];
    const float* mask  = (const float*)d_in[1];
    const float* h0    = (const float*)d_in[2];
    const float* c0    = (const float*)d_in[3];
    const float* W_ih  = (const float*)d_in[4];
    const float* W_hh  = (const float*)d_in[5];
    const float* b_ih  = (const float*)d_in[6];
    const float* b_hh  = (const float*)d_in[7];
    const float* W_x   = (const float*)d_in[8];
    const float* W_z   = (const float*)d_in[9];
    const float* w_c   = (const float*)d_in[10];
    const float* b_attn= (const float*)d_in[11];
    const float* v     = (const float*)d_in[12];
    float* out = (float*)d_out;

    int T = (out_size - 1) / (B_ * (DK_ + N_));

    zfea_kernel<<<(B_*N_)/64, 256>>>(z, W_z, b_attn);
    persistent_kernel<<<GRID_, 256>>>(out, T, out_size,
                                      W_ih, W_hh, b_ih, b_hh, W_x,
                                      mask, w_c, v, h0, c0);
}